// round 12
// baseline (speedup 1.0000x reference)
#include <cuda_runtime.h>
#include <cstdint>
#include <cstddef>

#define Bn 256
#define Ln 1024
#define Vn 40
#define Hn 128

// ---- packed f32x2 helpers (FFMA2 only reachable via PTX) ----
__device__ __forceinline__ unsigned long long ffma2(unsigned long long a,
                                                    unsigned long long b,
                                                    unsigned long long c) {
    unsigned long long d;
    asm("fma.rn.f32x2 %0, %1, %2, %3;" : "=l"(d) : "l"(a), "l"(b), "l"(c));
    return d;
}
__device__ __forceinline__ unsigned long long add2(unsigned long long a,
                                                   unsigned long long b) {
    unsigned long long d;
    asm("add.rn.f32x2 %0, %1, %2;" : "=l"(d) : "l"(a), "l"(b));
    return d;
}
__device__ __forceinline__ float plo(unsigned long long a) {
    return __int_as_float((int)(unsigned)(a & 0xffffffffull));
}
__device__ __forceinline__ float phi(unsigned long long a) {
    return __int_as_float((int)(unsigned)(a >> 32));
}
__device__ __forceinline__ float tanh_fast(float x) {
    float r;
    asm("tanh.approx.f32 %0, %1;" : "=f"(r) : "f"(x));
    return r;
}

// =====================================================================
// Fused CharRNN, high-occupancy version. 256 threads/CTA, one CTA per
// batch row; __launch_bounds__(256,2) caps regs at 128 so TWO CTAs
// co-reside -> 4 warps/SMSP (vs 2 before): latency finally hideable.
//
// Thread t (0..255):
//   h:     e = t&127, kh = t>>7. Partial of h elem e over k-half kh.
//          wh = Wh[e][64kh .. 64kh+64) in 32 u64 regs.
//   logit: v = t&63, q = t>>6 (warp-uniform). Partial of logit row v
//          over k-quarter q. wo = Wo[v][32q..32q+32) in 16 u64 regs
//          (zeros if v >= 40).
// Exchange: partner t^128 via double-buffered smem + __syncthreads.
// kh=0 folds em+bh pre-exchange and finalizes h elem t (tanh + STS).
// Logit: 4 quarter-partials reduced by threads with q==2 (v<40),
// off the h critical path. Iter l emits logit row l-1 (h loaded at
// iter l is the output of step l-1); row Ln-1 in an epilogue.
// =====================================================================
__global__ void __launch_bounds__(256, 2) fused_rnn_kernel(
    const int* __restrict__ x, const float* __restrict__ h0,
    const float* __restrict__ emb, const float* __restrict__ Wh,
    const float* __restrict__ Wo, const float* __restrict__ bh,
    const float* __restrict__ by, float* __restrict__ out,
    float* __restrict__ final_h)
{
    __shared__ __align__(16) float s_emb[Vn * Hn];   // 20 KB
    __shared__ int s_x[Ln];                          // 4 KB
    __shared__ __align__(16) float s_h[2][Hn];       // ping-pong h
    __shared__ float s_hp[2][256];                   // h partials (dbl-buf)
    __shared__ float s_lp[2][256];                   // logit partials (dbl-buf)

    const int t  = threadIdx.x;
    const int b  = blockIdx.x;
    const int e  = t & 127;          // h element
    const int kh = t >> 7;           // k-half for h (warp-uniform)
    const int v  = t & 63;           // logit row candidate
    const int q  = t >> 6;           // k-quarter for logit (warp-uniform)
    const bool dv = (v < Vn);

    for (int i = t; i < Vn * Hn; i += 256) s_emb[i] = emb[i];
    for (int i = t; i < Ln; i += 256) s_x[i] = x[b * Ln + i];
    if (t < Hn) s_h[0][t] = h0[b * Hn + t];
    const float bh_e = bh[e];
    const float byv  = dv ? by[v] : 0.f;

    // wh: Wh row e, k-half kh -> 32 u64 (64 regs)
    unsigned long long wh[32];
    {
        const ulonglong2* wp = (const ulonglong2*)(Wh + e * Hn + kh * 64);
#pragma unroll
        for (int i = 0; i < 16; i++) {
            ulonglong2 p = wp[i];
            wh[2 * i] = p.x; wh[2 * i + 1] = p.y;
        }
    }
    // wo: Wo row v, k-quarter q -> 16 u64 (32 regs), zeros if !dv
    unsigned long long wo[16];
    if (dv) {
        const ulonglong2* wv = (const ulonglong2*)(Wo + v * Hn + q * 32);
#pragma unroll
        for (int i = 0; i < 8; i++) {
            ulonglong2 p = wv[i];
            wo[2 * i] = p.x; wo[2 * i + 1] = p.y;
        }
    } else {
#pragma unroll
        for (int i = 0; i < 16; i++) wo[i] = 0ull;
    }
    __syncthreads();

    float* obase = out + (size_t)b * Ln * Vn;

    // em+bh prefolded, prefetched one step ahead (kh=0 threads only)
    float em_c = 0.f;
    if (kh == 0) em_c = s_emb[s_x[0] * Hn + e] + bh_e;

#pragma unroll 1
    for (int l = 0; l < Ln; l++) {
        const int buf = l & 1;
        // h entering step l == output of step l-1 (LDS.128 broadcast)
        const ulonglong2* hp  = (const ulonglong2*)(s_h[buf]) + kh * 16;
        const ulonglong2* hpq = (const ulonglong2*)(s_h[buf]) + q * 8;

        unsigned long long a0 = 0, a1 = 0;   // h elem e, my k-half
#pragma unroll
        for (int i = 0; i < 16; i++) {
            ulonglong2 p = hp[i];            // LDS.128 -> 2 FFMA2
            a0 = ffma2(wh[2 * i],     p.x, a0);
            a1 = ffma2(wh[2 * i + 1], p.y, a1);
        }
        unsigned long long g0 = 0, g1 = 0;   // logit row v, my k-quarter
#pragma unroll
        for (int i = 0; i < 8; i++) {
            ulonglong2 p = hpq[i];
            g0 = ffma2(wo[2 * i],     p.x, g0);
            g1 = ffma2(wo[2 * i + 1], p.y, g1);
        }
        a0 = add2(a0, a1);
        g0 = add2(g0, g1);
        float pe = plo(a0) + phi(a0);
        const float lp = plo(g0) + phi(g0);
        if (kh == 0) pe += em_c;             // fold em + bh exactly once

        s_hp[buf][t] = pe;
        s_lp[buf][t] = lp;

        // prefetch em+bh for step l+1 (hidden by the barrier)
        if (kh == 0) em_c = s_emb[s_x[(l + 1) & (Ln - 1)] * Hn + e] + bh_e;

        __syncthreads();                     // BAR1: partials published

        if (kh == 0) {                       // finalize h elem t
            const float hn = tanh_fast(pe + s_hp[buf][t + 128]);
            s_h[buf ^ 1][t] = hn;            // coalesced STS.32
        } else if (q == 2 && dv && l > 0) {  // finalize logit row l-1
            obase[(size_t)(l - 1) * Vn + v] =
                s_lp[buf][v] + s_lp[buf][v + 64] +
                s_lp[buf][v + 128] + s_lp[buf][v + 192] + byv;
        }
        __syncthreads();                     // BAR2: s_h ready
    }

    // Epilogue: logit row Ln-1 from the final hidden state (s_h[0]).
    {
        const ulonglong2* hpq = (const ulonglong2*)(s_h[0]) + q * 8;
        unsigned long long g0 = 0, g1 = 0;
#pragma unroll
        for (int i = 0; i < 8; i++) {
            ulonglong2 p = hpq[i];
            g0 = ffma2(wo[2 * i],     p.x, g0);
            g1 = ffma2(wo[2 * i + 1], p.y, g1);
        }
        g0 = add2(g0, g1);
        s_lp[0][t] = plo(g0) + phi(g0);
        __syncthreads();
        if (q == 2 && dv) {
            obase[(size_t)(Ln - 1) * Vn + v] =
                s_lp[0][v] + s_lp[0][v + 64] +
                s_lp[0][v + 128] + s_lp[0][v + 192] + byv;
        }
    }

    // Ln even -> final state in buffer 0
    if (t < Hn) final_h[b * Hn + t] = s_h[0][t];
}

extern "C" void kernel_launch(void* const* d_in, const int* in_sizes, int n_in,
                              void* d_out, int out_size)
{
    const int*   x   = (const int*)d_in[0];
    const float* h0  = (const float*)d_in[1];
    const float* emb = (const float*)d_in[2];
    const float* Wh  = (const float*)d_in[3];
    const float* Wo  = (const float*)d_in[4];
    const float* bh  = (const float*)d_in[5];
    const float* by  = (const float*)d_in[6];

    float* out     = (float*)d_out;
    float* logits  = out;                               // [B, L, V]
    float* final_h = out + (size_t)Bn * Ln * Vn;        // [B, H]

    fused_rnn_kernel<<<Bn, 256>>>(x, h0, emb, Wh, Wo, bh, by, logits, final_h);
}

// round 13
// speedup vs baseline: 1.0028x; 1.0028x over previous
#include <cuda_runtime.h>
#include <cstdint>
#include <cstddef>

#define Bn 256
#define Ln 1024
#define Vn 40
#define Hn 128

// ---- packed f32x2 helpers (FFMA2 only reachable via PTX) ----
__device__ __forceinline__ unsigned long long ffma2(unsigned long long a,
                                                    unsigned long long b,
                                                    unsigned long long c) {
    unsigned long long d;
    asm("fma.rn.f32x2 %0, %1, %2, %3;" : "=l"(d) : "l"(a), "l"(b), "l"(c));
    return d;
}
__device__ __forceinline__ unsigned long long add2(unsigned long long a,
                                                   unsigned long long b) {
    unsigned long long d;
    asm("add.rn.f32x2 %0, %1, %2;" : "=l"(d) : "l"(a), "l"(b));
    return d;
}
__device__ __forceinline__ float plo(unsigned long long a) {
    return __int_as_float((int)(unsigned)(a & 0xffffffffull));
}
__device__ __forceinline__ float phi(unsigned long long a) {
    return __int_as_float((int)(unsigned)(a >> 32));
}
__device__ __forceinline__ float tanh_fast(float x) {
    float r;
    asm("tanh.approx.f32 %0, %1;" : "=f"(r) : "f"(x));
    return r;
}

// =====================================================================
// Fused CharRNN, high-occupancy version. 256 threads/CTA, one CTA per
// batch row; __launch_bounds__(256,2) caps regs at 128 so TWO CTAs
// co-reside -> 4 warps/SMSP (vs 2 before): latency finally hideable.
//
// Thread t (0..255):
//   h:     e = t&127, kh = t>>7. Partial of h elem e over k-half kh.
//          wh = Wh[e][64kh .. 64kh+64) in 32 u64 regs.
//   logit: v = t&63, q = t>>6 (warp-uniform). Partial of logit row v
//          over k-quarter q. wo = Wo[v][32q..32q+32) in 16 u64 regs
//          (zeros if v >= 40).
// Exchange: partner t^128 via double-buffered smem + __syncthreads.
// kh=0 folds em+bh pre-exchange and finalizes h elem t (tanh + STS).
// Logit: 4 quarter-partials reduced by threads with q==2 (v<40),
// off the h critical path. Iter l emits logit row l-1 (h loaded at
// iter l is the output of step l-1); row Ln-1 in an epilogue.
// =====================================================================
__global__ void __launch_bounds__(256, 2) fused_rnn_kernel(
    const int* __restrict__ x, const float* __restrict__ h0,
    const float* __restrict__ emb, const float* __restrict__ Wh,
    const float* __restrict__ Wo, const float* __restrict__ bh,
    const float* __restrict__ by, float* __restrict__ out,
    float* __restrict__ final_h)
{
    __shared__ __align__(16) float s_emb[Vn * Hn];   // 20 KB
    __shared__ int s_x[Ln];                          // 4 KB
    __shared__ __align__(16) float s_h[2][Hn];       // ping-pong h
    __shared__ float s_hp[2][256];                   // h partials (dbl-buf)
    __shared__ float s_lp[2][256];                   // logit partials (dbl-buf)

    const int t  = threadIdx.x;
    const int b  = blockIdx.x;
    const int e  = t & 127;          // h element
    const int kh = t >> 7;           // k-half for h (warp-uniform)
    const int v  = t & 63;           // logit row candidate
    const int q  = t >> 6;           // k-quarter for logit (warp-uniform)
    const bool dv = (v < Vn);

    for (int i = t; i < Vn * Hn; i += 256) s_emb[i] = emb[i];
    for (int i = t; i < Ln; i += 256) s_x[i] = x[b * Ln + i];
    if (t < Hn) s_h[0][t] = h0[b * Hn + t];
    const float bh_e = bh[e];
    const float byv  = dv ? by[v] : 0.f;

    // wh: Wh row e, k-half kh -> 32 u64 (64 regs)
    unsigned long long wh[32];
    {
        const ulonglong2* wp = (const ulonglong2*)(Wh + e * Hn + kh * 64);
#pragma unroll
        for (int i = 0; i < 16; i++) {
            ulonglong2 p = wp[i];
            wh[2 * i] = p.x; wh[2 * i + 1] = p.y;
        }
    }
    // wo: Wo row v, k-quarter q -> 16 u64 (32 regs), zeros if !dv
    unsigned long long wo[16];
    if (dv) {
        const ulonglong2* wv = (const ulonglong2*)(Wo + v * Hn + q * 32);
#pragma unroll
        for (int i = 0; i < 8; i++) {
            ulonglong2 p = wv[i];
            wo[2 * i] = p.x; wo[2 * i + 1] = p.y;
        }
    } else {
#pragma unroll
        for (int i = 0; i < 16; i++) wo[i] = 0ull;
    }
    __syncthreads();

    float* obase = out + (size_t)b * Ln * Vn;

    // em+bh prefolded, prefetched one step ahead (kh=0 threads only)
    float em_c = 0.f;
    if (kh == 0) em_c = s_emb[s_x[0] * Hn + e] + bh_e;

#pragma unroll 1
    for (int l = 0; l < Ln; l++) {
        const int buf = l & 1;
        // h entering step l == output of step l-1 (LDS.128 broadcast)
        const ulonglong2* hp  = (const ulonglong2*)(s_h[buf]) + kh * 16;
        const ulonglong2* hpq = (const ulonglong2*)(s_h[buf]) + q * 8;

        unsigned long long a0 = 0, a1 = 0;   // h elem e, my k-half
#pragma unroll
        for (int i = 0; i < 16; i++) {
            ulonglong2 p = hp[i];            // LDS.128 -> 2 FFMA2
            a0 = ffma2(wh[2 * i],     p.x, a0);
            a1 = ffma2(wh[2 * i + 1], p.y, a1);
        }
        unsigned long long g0 = 0, g1 = 0;   // logit row v, my k-quarter
#pragma unroll
        for (int i = 0; i < 8; i++) {
            ulonglong2 p = hpq[i];
            g0 = ffma2(wo[2 * i],     p.x, g0);
            g1 = ffma2(wo[2 * i + 1], p.y, g1);
        }
        a0 = add2(a0, a1);
        g0 = add2(g0, g1);
        float pe = plo(a0) + phi(a0);
        const float lp = plo(g0) + phi(g0);
        if (kh == 0) pe += em_c;             // fold em + bh exactly once

        s_hp[buf][t] = pe;
        s_lp[buf][t] = lp;

        // prefetch em+bh for step l+1 (hidden by the barrier)
        if (kh == 0) em_c = s_emb[s_x[(l + 1) & (Ln - 1)] * Hn + e] + bh_e;

        __syncthreads();                     // BAR1: partials published

        if (kh == 0) {                       // finalize h elem t
            const float hn = tanh_fast(pe + s_hp[buf][t + 128]);
            s_h[buf ^ 1][t] = hn;            // coalesced STS.32
        } else if (q == 2 && dv && l > 0) {  // finalize logit row l-1
            obase[(size_t)(l - 1) * Vn + v] =
                s_lp[buf][v] + s_lp[buf][v + 64] +
                s_lp[buf][v + 128] + s_lp[buf][v + 192] + byv;
        }
        __syncthreads();                     // BAR2: s_h ready
    }

    // Epilogue: logit row Ln-1 from the final hidden state (s_h[0]).
    {
        const ulonglong2* hpq = (const ulonglong2*)(s_h[0]) + q * 8;
        unsigned long long g0 = 0, g1 = 0;
#pragma unroll
        for (int i = 0; i < 8; i++) {
            ulonglong2 p = hpq[i];
            g0 = ffma2(wo[2 * i],     p.x, g0);
            g1 = ffma2(wo[2 * i + 1], p.y, g1);
        }
        g0 = add2(g0, g1);
        s_lp[0][t] = plo(g0) + phi(g0);
        __syncthreads();
        if (q == 2 && dv) {
            obase[(size_t)(Ln - 1) * Vn + v] =
                s_lp[0][v] + s_lp[0][v + 64] +
                s_lp[0][v + 128] + s_lp[0][v + 192] + byv;
        }
    }

    // Ln even -> final state in buffer 0
    if (t < Hn) final_h[b * Hn + t] = s_h[0][t];
}

extern "C" void kernel_launch(void* const* d_in, const int* in_sizes, int n_in,
                              void* d_out, int out_size)
{
    const int*   x   = (const int*)d_in[0];
    const float* h0  = (const float*)d_in[1];
    const float* emb = (const float*)d_in[2];
    const float* Wh  = (const float*)d_in[3];
    const float* Wo  = (const float*)d_in[4];
    const float* bh  = (const float*)d_in[5];
    const float* by  = (const float*)d_in[6];

    float* out     = (float*)d_out;
    float* logits  = out;                               // [B, L, V]
    float* final_h = out + (size_t)Bn * Ln * Vn;        // [B, H]

    fused_rnn_kernel<<<Bn, 256>>>(x, h0, emb, Wh, Wo, bh, by, logits, final_h);
}

// round 14
// speedup vs baseline: 1.3683x; 1.3646x over previous
#include <cuda_runtime.h>
#include <cstdint>
#include <cstddef>

#define Bn 256
#define Ln 1024
#define Vn 40
#define Hn 128

// ---- packed f32x2 helpers (FFMA2 only reachable via PTX) ----
__device__ __forceinline__ unsigned long long ffma2(unsigned long long a,
                                                    unsigned long long b,
                                                    unsigned long long c) {
    unsigned long long d;
    asm("fma.rn.f32x2 %0, %1, %2, %3;" : "=l"(d) : "l"(a), "l"(b), "l"(c));
    return d;
}
__device__ __forceinline__ unsigned long long add2(unsigned long long a,
                                                   unsigned long long b) {
    unsigned long long d;
    asm("add.rn.f32x2 %0, %1, %2;" : "=l"(d) : "l"(a), "l"(b));
    return d;
}
__device__ __forceinline__ float plo(unsigned long long a) {
    return __int_as_float((int)(unsigned)(a & 0xffffffffull));
}
__device__ __forceinline__ float phi(unsigned long long a) {
    return __int_as_float((int)(unsigned)(a >> 32));
}
__device__ __forceinline__ float tanh_fast(float x) {
    float r;
    asm("tanh.approx.f32 %0, %1;" : "=f"(r) : "f"(x));
    return r;
}

// =====================================================================
// Fused CharRNN (R7 dataflow + deferred logit store). One CTA per
// batch row, 128 threads. Thread t: e0 = t&63, kh = t>>6 (warp-
// uniform). Per step: half-k partials for h elems e0, e0+64 and logit
// v=e0 (zero-padded v>=40) -- 96 FFMA2 off 16 LDS.128 broadcasts.
//
// KEY CHANGE vs R7: the logit finalize/STG no longer sits between
// BAR1 and BAR2. Logit partials go to double-buffered slp[l&1]; the
// store of row l-2 happens at the TOP of iteration l, overlapped with
// the FFMA phase. The BAR1->BAR2 window is now exactly:
//   LDS.32 (partner partial) + FADD + tanh + STS.32(h)
// Logit timing: partials at iter j come from h_{j-1} -> row j-1;
// stored at iter j+1 (row (l=j+1)-2 = j-1 OK). Epilogue emits row
// Ln-2 (buffered) and row Ln-1 (fresh pass over final h).
// =====================================================================
__global__ void __launch_bounds__(128, 2) fused_rnn_kernel(
    const int* __restrict__ x, const float* __restrict__ h0,
    const float* __restrict__ emb, const float* __restrict__ Wh,
    const float* __restrict__ Wo, const float* __restrict__ bh,
    const float* __restrict__ by, float* __restrict__ out,
    float* __restrict__ final_h)
{
    __shared__ __align__(16) float s_emb[Vn * Hn];   // 20 KB
    __shared__ int s_x[Ln];                          // 4 KB
    __shared__ __align__(16) float s_h[2][Hn];       // ping-pong h
    __shared__ __align__(16) float4 s_red[128];      // {pe0, pe1} exchange
    __shared__ float slp[2][Hn];                     // logit partials, dbl-buf

    const int t  = threadIdx.x;
    const int b  = blockIdx.x;
    const int e0 = t & 63;
    const int kh = t >> 6;                            // warp-uniform

    for (int i = t; i < Vn * Hn; i += 128) s_emb[i] = emb[i];
    for (int i = t; i < Ln; i += 128) s_x[i] = x[b * Ln + i];
    s_h[0][t] = h0[b * Hn + t];
    const float bh0 = bh[e0];
    const float bh1 = bh[e0 + 64];
    const bool  dv  = (e0 < Vn);
    const float byv = dv ? by[e0] : 0.f;

    // wh[0..31]: Wh row e0, cols [64kh,64kh+64); wh[32..63]: row e0+64
    unsigned long long wh[64];
    {
        const ulonglong2* w0 = (const ulonglong2*)(Wh + e0 * Hn + kh * 64);
        const ulonglong2* w1 = (const ulonglong2*)(Wh + (e0 + 64) * Hn + kh * 64);
#pragma unroll
        for (int i = 0; i < 16; i++) {
            ulonglong2 p = w0[i];
            wh[2 * i] = p.x; wh[2 * i + 1] = p.y;
        }
#pragma unroll
        for (int i = 0; i < 16; i++) {
            ulonglong2 p = w1[i];
            wh[32 + 2 * i] = p.x; wh[33 + 2 * i] = p.y;
        }
    }
    // wo[0..31]: Wo row v=e0, cols [64kh,64kh+64) (zeros if v >= 40)
    unsigned long long wo[32];
    if (dv) {
        const ulonglong2* wv = (const ulonglong2*)(Wo + e0 * Hn + kh * 64);
#pragma unroll
        for (int i = 0; i < 16; i++) {
            ulonglong2 p = wv[i];
            wo[2 * i] = p.x; wo[2 * i + 1] = p.y;
        }
    } else {
#pragma unroll
        for (int i = 0; i < 32; i++) wo[i] = 0ull;
    }
    __syncthreads();

    float* obase = out + (size_t)b * Ln * Vn;

    // Prefetch embedding terms for step 0 (kh=0 warps; warp-uniform)
    float em0c = 0.f, em1c = 0.f;
    if (kh == 0) {
        const int idx0 = s_x[0];
        em0c = s_emb[idx0 * Hn + e0];
        em1c = s_emb[idx0 * Hn + e0 + 64];
    }

#pragma unroll 1
    for (int l = 0; l < Ln; l++) {
        const int buf = l & 1;

        // Deferred logit store: row l-2 from partials buffered at iter l-1.
        // Overlaps the FFMA phase; kh=1 threads (kh=0 does em prefetch).
        if (kh == 1 && dv && l >= 2) {
            obase[(size_t)(l - 2) * Vn + e0] =
                slp[buf ^ 1][e0] + slp[buf ^ 1][e0 + 64] + byv;
        }

        // h entering step l == output of step l-1 (LDS.128 broadcast)
        const ulonglong2* hp = (const ulonglong2*)(s_h[buf]) + kh * 16;

        unsigned long long a0 = 0, a1 = 0;   // h elem e0
        unsigned long long c0 = 0, c1 = 0;   // h elem e0+64
        unsigned long long g0 = 0, g1 = 0;   // logit v=e0 (row l-1)
#pragma unroll
        for (int i = 0; i < 16; i++) {
            ulonglong2 p = hp[i];            // LDS.128 -> feeds 6 FFMA2
            a0 = ffma2(wh[2 * i],      p.x, a0);
            c0 = ffma2(wh[32 + 2 * i], p.x, c0);
            g0 = ffma2(wo[2 * i],      p.x, g0);
            a1 = ffma2(wh[2 * i + 1],  p.y, a1);
            c1 = ffma2(wh[33 + 2 * i], p.y, c1);
            g1 = ffma2(wo[2 * i + 1],  p.y, g1);
        }
        a0 = add2(a0, a1);
        c0 = add2(c0, c1);
        g0 = add2(g0, g1);
        float pe0 = plo(a0) + phi(a0);
        float pe1 = plo(c0) + phi(c0);
        slp[buf][t] = plo(g0) + phi(g0);      // logit partial (read at l+1)

        if (kh == 0) {                        // fold em + bh exactly once
            pe0 += em0c + bh0;
            pe1 += em1c + bh1;
        }
        s_red[t] = make_float4(pe0, pe1, 0.f, 0.f);

        // Register-prefetch embedding for step l+1 (hidden by BAR)
        if (kh == 0) {
            const int idxn = s_x[(l + 1) & (Ln - 1)];
            em0c = s_emb[idxn * Hn + e0];
            em1c = s_emb[idxn * Hn + e0 + 64];
        }
        __syncthreads();                      // BAR1: partials published

        // Minimal window: every thread finalizes elem t
        const float mine  = (kh == 0) ? pe0 : pe1;
        const float other = ((const float*)s_red)[((t ^ 64) << 2) + kh];
        s_h[buf ^ 1][t] = tanh_fast(mine + other);   // STS.32

        __syncthreads();                      // BAR2: s_h ready
    }

    // Epilogue 1: logit row Ln-2 from partials buffered at iter Ln-1.
    if (kh == 1 && dv) {
        obase[(size_t)(Ln - 2) * Vn + e0] =
            slp[(Ln - 1) & 1][e0] + slp[(Ln - 1) & 1][e0 + 64] + byv;
    }

    // Epilogue 2: logit row Ln-1 from the final hidden state (s_h[0]).
    {
        const ulonglong2* hp = (const ulonglong2*)(s_h[0]) + kh * 16;
        unsigned long long g0 = 0, g1 = 0;
#pragma unroll
        for (int i = 0; i < 16; i++) {
            ulonglong2 p = hp[i];
            g0 = ffma2(wo[2 * i],     p.x, g0);
            g1 = ffma2(wo[2 * i + 1], p.y, g1);
        }
        g0 = add2(g0, g1);
        slp[0][t] = plo(g0) + phi(g0);
        __syncthreads();
        if (kh == 1 && dv) {
            obase[(size_t)(Ln - 1) * Vn + e0] =
                slp[0][e0] + slp[0][e0 + 64] + byv;
        }
    }

    final_h[b * Hn + t] = s_h[0][t];   // Ln even -> final state in buffer 0
}

extern "C" void kernel_launch(void* const* d_in, const int* in_sizes, int n_in,
                              void* d_out, int out_size)
{
    const int*   x   = (const int*)d_in[0];
    const float* h0  = (const float*)d_in[1];
    const float* emb = (const float*)d_in[2];
    const float* Wh  = (const float*)d_in[3];
    const float* Wo  = (const float*)d_in[4];
    const float* bh  = (const float*)d_in[5];
    const float* by  = (const float*)d_in[6];

    float* out     = (float*)d_out;
    float* logits  = out;                               // [B, L, V]
    float* final_h = out + (size_t)Bn * Ln * Vn;        // [B, H]

    fused_rnn_kernel<<<Bn, 128>>>(x, h0, emb, Wh, Wo, bh, by, logits, final_h);
}